// round 1
// baseline (speedup 1.0000x reference)
#include <cuda_runtime.h>
#include <math.h>

#define NN 200000
#define NE 6400000
#define NG 64

// scratch (device globals — no allocation allowed)
__device__ float g_acc1[NN * 12];     // cols 0..10 = sum(msg1), col 11 = degree
__device__ float g_deg[NN];
__device__ float g_h1[NN * 32];
__device__ float g_acc2[NN * 32];
__device__ float g_pooled[NG * 32];

__global__ void zero_kernel(int total) {
    int i = blockIdx.x * blockDim.x + threadIdx.x;
    int stride = gridDim.x * blockDim.x;
    const int n1 = NN * 12;
    const int n2 = NN * 32;
    for (; i < total; i += stride) {
        if (i < n1) g_acc1[i] = 0.0f;
        else if (i < n1 + n2) g_acc2[i - n1] = 0.0f;
        else g_pooled[i - n1 - n2] = 0.0f;
    }
}

// Edge pass 1: 12 threads per edge. f in [0,11].
// f<4: edge_feat, 4<=f<11: node_feat[src], f==11: degree (1.0)
__global__ void edge1_kernel(const float* __restrict__ edge_feat,
                             const float* __restrict__ node_feat,
                             const int* __restrict__ src,
                             const int* __restrict__ dst) {
    long long i = (long long)blockIdx.x * blockDim.x + threadIdx.x;
    if (i >= (long long)NE * 12) return;
    int e = (int)(i / 12);
    int f = (int)(i % 12);
    int d = dst[e];
    float val;
    if (f < 4) {
        val = edge_feat[e * 4 + f];
    } else if (f < 11) {
        int s = src[e];
        val = node_feat[s * 7 + (f - 4)];
    } else {
        val = 1.0f;
    }
    atomicAdd(&g_acc1[d * 12 + f], val);
}

// Node pass 1: one warp per node. MLP 11->32 relu -> 32->32 relu.
__global__ void node1_kernel(const float* __restrict__ W1a, const float* __restrict__ b1a,
                             const float* __restrict__ W1b, const float* __restrict__ b1b) {
    __shared__ float sW1a[11 * 32];
    __shared__ float sb1a[32];
    __shared__ float sW1b[32 * 32];
    __shared__ float sb1b[32];
    int tid = threadIdx.x;
    for (int k = tid; k < 11 * 32; k += blockDim.x) sW1a[k] = W1a[k];
    for (int k = tid; k < 32 * 32; k += blockDim.x) sW1b[k] = W1b[k];
    if (tid < 32) { sb1a[tid] = b1a[tid]; sb1b[tid] = b1b[tid]; }
    __syncthreads();

    int warp = tid >> 5;
    int lane = tid & 31;
    int n = blockIdx.x * (blockDim.x >> 5) + warp;
    if (n >= NN) return;

    float deg = g_acc1[n * 12 + 11];
    float invd = 1.0f / fmaxf(deg, 1.0f);
    float x = (lane < 11) ? g_acc1[n * 12 + lane] * invd : 0.0f;

    // y[lane] = relu(b1a[lane] + sum_k x[k] * W1a[k][lane])
    float y = sb1a[lane];
#pragma unroll
    for (int k = 0; k < 11; k++) {
        float xk = __shfl_sync(0xffffffffu, x, k);
        y = fmaf(xk, sW1a[k * 32 + lane], y);
    }
    y = fmaxf(y, 0.0f);

    float z = sb1b[lane];
#pragma unroll
    for (int k = 0; k < 32; k++) {
        float yk = __shfl_sync(0xffffffffu, y, k);
        z = fmaf(yk, sW1b[k * 32 + lane], z);
    }
    z = fmaxf(z, 0.0f);

    g_h1[n * 32 + lane] = z;
    if (lane == 0) g_deg[n] = deg;
}

// Edge pass 2: one warp per edge, lane = feature. Coalesced gather + coalesced atomic scatter.
__global__ void edge2_kernel(const int* __restrict__ src,
                             const int* __restrict__ dst) {
    long long i = (long long)blockIdx.x * blockDim.x + threadIdx.x;
    if (i >= (long long)NE * 32) return;
    int e = (int)(i >> 5);
    int lane = (int)(i & 31);
    int s = src[e];
    int d = dst[e];
    float val = g_h1[s * 32 + lane];
    atomicAdd(&g_acc2[d * 32 + lane], val);
}

// Node pass 2: warp per node, MLP 32->32 relu ->32->32 relu, then pooled max (values >= 0).
__global__ void node2_kernel(const float* __restrict__ W2a, const float* __restrict__ b2a,
                             const float* __restrict__ W2b, const float* __restrict__ b2b,
                             const int* __restrict__ graph_ids) {
    __shared__ float sW2a[32 * 32];
    __shared__ float sb2a[32];
    __shared__ float sW2b[32 * 32];
    __shared__ float sb2b[32];
    int tid = threadIdx.x;
    for (int k = tid; k < 32 * 32; k += blockDim.x) { sW2a[k] = W2a[k]; sW2b[k] = W2b[k]; }
    if (tid < 32) { sb2a[tid] = b2a[tid]; sb2b[tid] = b2b[tid]; }
    __syncthreads();

    int warp = tid >> 5;
    int lane = tid & 31;
    int n = blockIdx.x * (blockDim.x >> 5) + warp;
    if (n >= NN) return;

    float invd = 1.0f / fmaxf(g_deg[n], 1.0f);
    float x = g_acc2[n * 32 + lane] * invd;

    float y = sb2a[lane];
#pragma unroll
    for (int k = 0; k < 32; k++) {
        float xk = __shfl_sync(0xffffffffu, x, k);
        y = fmaf(xk, sW2a[k * 32 + lane], y);
    }
    y = fmaxf(y, 0.0f);

    float z = sb2b[lane];
#pragma unroll
    for (int k = 0; k < 32; k++) {
        float yk = __shfl_sync(0xffffffffu, y, k);
        z = fmaf(yk, sW2b[k * 32 + lane], z);
    }
    z = fmaxf(z, 0.0f);  // z >= 0 -> int-compare atomicMax is valid

    int g = graph_ids[n];
    atomicMax((int*)&g_pooled[g * 32 + lane], __float_as_int(z));
}

// Final: 64 threads, one per graph. 32->16 relu -> 16->2, softmax.
__global__ void head_kernel(const float* __restrict__ Wm1, const float* __restrict__ bm1,
                            const float* __restrict__ Wm2, const float* __restrict__ bm2,
                            float* __restrict__ out) {
    int g = threadIdx.x;
    if (g >= NG) return;
    float p[32];
#pragma unroll
    for (int k = 0; k < 32; k++) p[k] = g_pooled[g * 32 + k];
    float hid[16];
#pragma unroll
    for (int j = 0; j < 16; j++) {
        float acc = bm1[j];
#pragma unroll
        for (int k = 0; k < 32; k++) acc = fmaf(p[k], Wm1[k * 16 + j], acc);
        hid[j] = fmaxf(acc, 0.0f);
    }
    float l0 = bm2[0], l1 = bm2[1];
#pragma unroll
    for (int j = 0; j < 16; j++) {
        l0 = fmaf(hid[j], Wm2[j * 2 + 0], l0);
        l1 = fmaf(hid[j], Wm2[j * 2 + 1], l1);
    }
    float m = fmaxf(l0, l1);
    float e0 = expf(l0 - m);
    float e1 = expf(l1 - m);
    float inv = 1.0f / (e0 + e1);
    out[g * 2 + 0] = e0 * inv;
    out[g * 2 + 1] = e1 * inv;
}

extern "C" void kernel_launch(void* const* d_in, const int* in_sizes, int n_in,
                              void* d_out, int out_size) {
    const float* node_feat = (const float*)d_in[0];
    const float* edge_feat = (const float*)d_in[1];
    const int*   src       = (const int*)d_in[2];
    const int*   dst       = (const int*)d_in[3];
    const int*   graph_ids = (const int*)d_in[4];
    const float* W1a = (const float*)d_in[5];
    const float* b1a = (const float*)d_in[6];
    const float* W1b = (const float*)d_in[7];
    const float* b1b = (const float*)d_in[8];
    const float* W2a = (const float*)d_in[9];
    const float* b2a = (const float*)d_in[10];
    const float* W2b = (const float*)d_in[11];
    const float* b2b = (const float*)d_in[12];
    const float* Wm1 = (const float*)d_in[13];
    const float* bm1 = (const float*)d_in[14];
    const float* Wm2 = (const float*)d_in[15];
    const float* bm2 = (const float*)d_in[16];
    float* out = (float*)d_out;

    // 1. zero scratch
    {
        int total = NN * 12 + NN * 32 + NG * 32;
        int blocks = (total + 255) / 256;
        if (blocks > 65535) blocks = 65535;
        zero_kernel<<<blocks, 256>>>(total);
    }
    // 2. edge pass 1 (12 threads/edge)
    {
        long long threads = (long long)NE * 12;
        int blocks = (int)((threads + 255) / 256);
        edge1_kernel<<<blocks, 256>>>(edge_feat, node_feat, src, dst);
    }
    // 3. node pass 1 (warp/node)
    {
        int warps_per_block = 8;
        int blocks = (NN + warps_per_block - 1) / warps_per_block;
        node1_kernel<<<blocks, 256>>>(W1a, b1a, W1b, b1b);
    }
    // 4. edge pass 2 (warp/edge)
    {
        long long threads = (long long)NE * 32;
        int blocks = (int)((threads + 255) / 256);
        edge2_kernel<<<blocks, 256>>>(src, dst);
    }
    // 5. node pass 2 + pooling
    {
        int warps_per_block = 8;
        int blocks = (NN + warps_per_block - 1) / warps_per_block;
        node2_kernel<<<blocks, 256>>>(W2a, b2a, W2b, b2b, graph_ids);
    }
    // 6. classifier head + softmax
    head_kernel<<<1, 64>>>(Wm1, bm1, Wm2, bm2, out);
}

// round 2
// speedup vs baseline: 1.9544x; 1.9544x over previous
#include <cuda_runtime.h>
#include <math.h>

#define NN 200000
#define NE 6400000
#define NG 64
#define NB_SCAN 782   // ceil(NN/256)

// ---- device scratch (static, no runtime allocation) ----
__device__ int   g_count[NN];       // in-degree
__device__ int   g_cursor[NN];      // scatter cursor
__device__ int   g_off[NN];         // CSR offsets (exclusive scan of count)
__device__ int   g_bsum[1024];      // scan block sums
__device__ int2  g_sorted[NE];      // (eid, src) sorted by dst
__device__ float g_nf8[NN * 8];     // node_feat padded to 8 floats/row
__device__ float g_h1[NN * 32];     // layer-1 output
__device__ float g_invd[NN];        // 1/max(deg,1)
__device__ float g_pooled[NG * 32];

// ---------------- setup ----------------
__global__ void zero_kernel() {
    int i = blockIdx.x * blockDim.x + threadIdx.x;
    int stride = gridDim.x * blockDim.x;
    const int total = 2 * NN + NG * 32;
    for (; i < total; i += stride) {
        if (i < NN) g_count[i] = 0;
        else if (i < 2 * NN) g_cursor[i - NN] = 0;
        else g_pooled[i - 2 * NN] = 0.0f;
    }
}

__global__ void pad_nf_kernel(const float* __restrict__ node_feat) {
    int i = blockIdx.x * blockDim.x + threadIdx.x;
    if (i >= NN * 8) return;
    int n = i >> 3, k = i & 7;
    g_nf8[i] = (k < 7) ? node_feat[n * 7 + k] : 0.0f;
}

// ---------------- counting sort by dst ----------------
__global__ void hist_kernel(const int* __restrict__ dst) {
    int e = blockIdx.x * blockDim.x + threadIdx.x;
    if (e >= NE) return;
    atomicAdd(&g_count[dst[e]], 1);
}

__global__ void scan_local_kernel() {
    __shared__ int s[256];
    int t = threadIdx.x;
    int i = blockIdx.x * 256 + t;
    int v = (i < NN) ? g_count[i] : 0;
    s[t] = v;
    __syncthreads();
    for (int off = 1; off < 256; off <<= 1) {
        int add = (t >= off) ? s[t - off] : 0;
        __syncthreads();
        s[t] += add;
        __syncthreads();
    }
    if (i < NN) g_off[i] = s[t] - v;          // exclusive
    if (t == 255) g_bsum[blockIdx.x] = s[255]; // block total
}

__global__ void scan_bsums_kernel() {
    __shared__ int s[1024];
    int t = threadIdx.x;
    int v = (t < NB_SCAN) ? g_bsum[t] : 0;
    s[t] = v;
    __syncthreads();
    for (int off = 1; off < 1024; off <<= 1) {
        int add = (t >= off) ? s[t - off] : 0;
        __syncthreads();
        s[t] += add;
        __syncthreads();
    }
    if (t < NB_SCAN) g_bsum[t] = s[t] - v;    // exclusive
}

__global__ void scan_add_kernel() {
    int i = blockIdx.x * 256 + threadIdx.x;
    if (i < NN) g_off[i] += g_bsum[blockIdx.x];
}

__global__ void scatter_kernel(const int* __restrict__ src,
                               const int* __restrict__ dst) {
    int e = blockIdx.x * blockDim.x + threadIdx.x;
    if (e >= NE) return;
    int d = dst[e];
    int pos = g_off[d] + atomicAdd(&g_cursor[d], 1);
    g_sorted[pos] = make_int2(e, src[e]);
}

// ---------------- layer 1: gather-reduce + MLP (warp per node) ----------------
__global__ void node1_kernel(const float4* __restrict__ ef4,
                             const float* __restrict__ W1a, const float* __restrict__ b1a,
                             const float* __restrict__ W1b, const float* __restrict__ b1b) {
    __shared__ float sW1a[11 * 32];
    __shared__ float sW1b[32 * 32];
    __shared__ float sb1a[32];
    __shared__ float sb1b[32];
    int tid = threadIdx.x;
    for (int k = tid; k < 11 * 32; k += blockDim.x) sW1a[k] = W1a[k];
    for (int k = tid; k < 32 * 32; k += blockDim.x) sW1b[k] = W1b[k];
    if (tid < 32) { sb1a[tid] = b1a[tid]; sb1b[tid] = b1b[tid]; }
    __syncthreads();

    int warp = tid >> 5;
    int lane = tid & 31;
    int n = blockIdx.x * (blockDim.x >> 5) + warp;
    if (n >= NN) return;

    int start = g_off[n];
    int deg   = g_count[n];

    float acc[11];
#pragma unroll
    for (int k = 0; k < 11; k++) acc[k] = 0.0f;

    const float4* nf4 = (const float4*)g_nf8;
    for (int j = lane; j < deg; j += 32) {
        int2 p = g_sorted[start + j];
        float4 ef = ef4[p.x];
        acc[0] += ef.x; acc[1] += ef.y; acc[2] += ef.z; acc[3] += ef.w;
        float4 a = nf4[p.y * 2];
        float4 b = nf4[p.y * 2 + 1];
        acc[4] += a.x; acc[5] += a.y; acc[6] += a.z; acc[7] += a.w;
        acc[8] += b.x; acc[9] += b.y; acc[10] += b.z;
    }

    // butterfly reduce across warp: every lane ends with the 11 totals
#pragma unroll
    for (int off = 16; off; off >>= 1) {
#pragma unroll
        for (int k = 0; k < 11; k++)
            acc[k] += __shfl_xor_sync(0xffffffffu, acc[k], off);
    }

    float invd = 1.0f / fmaxf((float)deg, 1.0f);

    float y = sb1a[lane];
#pragma unroll
    for (int k = 0; k < 11; k++)
        y = fmaf(acc[k] * invd, sW1a[k * 32 + lane], y);
    y = fmaxf(y, 0.0f);

    float z = sb1b[lane];
#pragma unroll
    for (int k = 0; k < 32; k++) {
        float yk = __shfl_sync(0xffffffffu, y, k);
        z = fmaf(yk, sW1b[k * 32 + lane], z);
    }
    z = fmaxf(z, 0.0f);

    g_h1[n * 32 + lane] = z;
    if (lane == 0) g_invd[n] = invd;
}

// ---------------- layer 2: gather-reduce + MLP + pool (warp per node) ----------------
__global__ void node2_kernel(const float* __restrict__ W2a, const float* __restrict__ b2a,
                             const float* __restrict__ W2b, const float* __restrict__ b2b,
                             const int* __restrict__ graph_ids) {
    __shared__ float sW2a[32 * 32];
    __shared__ float sW2b[32 * 32];
    __shared__ float sb2a[32];
    __shared__ float sb2b[32];
    int tid = threadIdx.x;
    for (int k = tid; k < 32 * 32; k += blockDim.x) { sW2a[k] = W2a[k]; sW2b[k] = W2b[k]; }
    if (tid < 32) { sb2a[tid] = b2a[tid]; sb2b[tid] = b2b[tid]; }
    __syncthreads();

    int warp = tid >> 5;
    int lane = tid & 31;
    int n = blockIdx.x * (blockDim.x >> 5) + warp;
    if (n >= NN) return;

    int start = g_off[n];
    int deg   = g_count[n];

    float acc0 = 0.0f, acc1 = 0.0f, acc2 = 0.0f, acc3 = 0.0f;
    int j = 0;
    for (; j + 4 <= deg; j += 4) {
        int s0 = g_sorted[start + j + 0].y;
        int s1 = g_sorted[start + j + 1].y;
        int s2 = g_sorted[start + j + 2].y;
        int s3 = g_sorted[start + j + 3].y;
        acc0 += g_h1[s0 * 32 + lane];
        acc1 += g_h1[s1 * 32 + lane];
        acc2 += g_h1[s2 * 32 + lane];
        acc3 += g_h1[s3 * 32 + lane];
    }
    for (; j < deg; j++) {
        int s = g_sorted[start + j].y;
        acc0 += g_h1[s * 32 + lane];
    }
    float x = ((acc0 + acc1) + (acc2 + acc3)) * g_invd[n];

    float y = sb2a[lane];
#pragma unroll
    for (int k = 0; k < 32; k++) {
        float xk = __shfl_sync(0xffffffffu, x, k);
        y = fmaf(xk, sW2a[k * 32 + lane], y);
    }
    y = fmaxf(y, 0.0f);

    float z = sb2b[lane];
#pragma unroll
    for (int k = 0; k < 32; k++) {
        float yk = __shfl_sync(0xffffffffu, y, k);
        z = fmaf(yk, sW2b[k * 32 + lane], z);
    }
    z = fmaxf(z, 0.0f);  // >= 0, so int-compare atomicMax is order-safe

    int g = graph_ids[n];
    atomicMax((int*)&g_pooled[g * 32 + lane], __float_as_int(z));
}

// ---------------- classifier head ----------------
__global__ void head_kernel(const float* __restrict__ Wm1, const float* __restrict__ bm1,
                            const float* __restrict__ Wm2, const float* __restrict__ bm2,
                            float* __restrict__ out) {
    int g = threadIdx.x;
    if (g >= NG) return;
    float p[32];
#pragma unroll
    for (int k = 0; k < 32; k++) p[k] = g_pooled[g * 32 + k];
    float hid[16];
#pragma unroll
    for (int jj = 0; jj < 16; jj++) {
        float a = bm1[jj];
#pragma unroll
        for (int k = 0; k < 32; k++) a = fmaf(p[k], Wm1[k * 16 + jj], a);
        hid[jj] = fmaxf(a, 0.0f);
    }
    float l0 = bm2[0], l1 = bm2[1];
#pragma unroll
    for (int jj = 0; jj < 16; jj++) {
        l0 = fmaf(hid[jj], Wm2[jj * 2 + 0], l0);
        l1 = fmaf(hid[jj], Wm2[jj * 2 + 1], l1);
    }
    float m = fmaxf(l0, l1);
    float e0 = expf(l0 - m);
    float e1 = expf(l1 - m);
    float inv = 1.0f / (e0 + e1);
    out[g * 2 + 0] = e0 * inv;
    out[g * 2 + 1] = e1 * inv;
}

extern "C" void kernel_launch(void* const* d_in, const int* in_sizes, int n_in,
                              void* d_out, int out_size) {
    const float* node_feat = (const float*)d_in[0];
    const float* edge_feat = (const float*)d_in[1];
    const int*   src       = (const int*)d_in[2];
    const int*   dst       = (const int*)d_in[3];
    const int*   graph_ids = (const int*)d_in[4];
    const float* W1a = (const float*)d_in[5];
    const float* b1a = (const float*)d_in[6];
    const float* W1b = (const float*)d_in[7];
    const float* b1b = (const float*)d_in[8];
    const float* W2a = (const float*)d_in[9];
    const float* b2a = (const float*)d_in[10];
    const float* W2b = (const float*)d_in[11];
    const float* b2b = (const float*)d_in[12];
    const float* Wm1 = (const float*)d_in[13];
    const float* bm1 = (const float*)d_in[14];
    const float* Wm2 = (const float*)d_in[15];
    const float* bm2 = (const float*)d_in[16];
    float* out = (float*)d_out;

    zero_kernel<<<512, 256>>>();
    pad_nf_kernel<<<(NN * 8 + 255) / 256, 256>>>(node_feat);
    hist_kernel<<<NE / 256, 256>>>(dst);
    scan_local_kernel<<<NB_SCAN, 256>>>();
    scan_bsums_kernel<<<1, 1024>>>();
    scan_add_kernel<<<NB_SCAN, 256>>>();
    scatter_kernel<<<NE / 256, 256>>>(src, dst);
    node1_kernel<<<NN / 8, 256>>>((const float4*)edge_feat, W1a, b1a, W1b, b1b);
    node2_kernel<<<NN / 8, 256>>>(W2a, b2a, W2b, b2b, graph_ids);
    head_kernel<<<1, 64>>>(Wm1, bm1, Wm2, bm2, out);
}